// round 4
// baseline (speedup 1.0000x reference)
#include <cuda_runtime.h>
#include <cuda_bf16.h>
#include <cstdint>
#include <cstddef>

// ---------------------------------------------------------------------------
// QUIK quantized linear, M = N = K = 4096.
//   1) global min/max of x and w            (atomic-encoded fp32 reduce)
//   2) quantize x -> bf16 ints in [-4,3]
//   3) quantize w -> bf16 ints, fused per-row fp32 sum (weights_reduced)
//   4) bf16 MMA GEMM (fp32 accum == exact integer GEMM) + dequant epilogue
// ---------------------------------------------------------------------------

#define MDIM 4096
#define NDIM 4096
#define KDIM 4096

#define BM 128
#define BN 128
#define BK 32
#define LDS_A 40   // BK + 8 pad (bf16 elems): conflict-free ldmatrix row pattern

// Scratch (device globals: allocation-free, harness-legal)
__device__ unsigned g_xmin_u, g_xmax_u, g_wmin_u, g_wmax_u;
__device__ __align__(16) __nv_bfloat16 g_xq[(size_t)MDIM * KDIM];
__device__ __align__(16) __nv_bfloat16 g_wq[(size_t)NDIM * KDIM];
__device__ float g_wsum[NDIM];

// ---- monotonic float <-> uint encoding for atomicMin/Max ----
__device__ __forceinline__ unsigned fenc(float f) {
    unsigned u = __float_as_uint(f);
    return (u & 0x80000000u) ? ~u : (u | 0x80000000u);
}
__device__ __forceinline__ float fdec(unsigned u) {
    u = (u & 0x80000000u) ? (u & 0x7FFFFFFFu) : ~u;
    return __uint_as_float(u);
}

__global__ void init_kernel() {
    g_xmin_u = 0xFFFFFFFFu; g_xmax_u = 0u;
    g_wmin_u = 0xFFFFFFFFu; g_wmax_u = 0u;
}

// ---------------------------------------------------------------------------
// Min/max reduction (sel: 0 = x globals, 1 = w globals)
// ---------------------------------------------------------------------------
__global__ void minmax_kernel(const float4* __restrict__ p, int n4, int sel) {
    float lmin =  3.402823466e38f;
    float lmax = -3.402823466e38f;
    for (int i = blockIdx.x * blockDim.x + threadIdx.x; i < n4;
         i += gridDim.x * blockDim.x) {
        float4 v = p[i];
        lmin = fminf(lmin, fminf(fminf(v.x, v.y), fminf(v.z, v.w)));
        lmax = fmaxf(lmax, fmaxf(fmaxf(v.x, v.y), fmaxf(v.z, v.w)));
    }
#pragma unroll
    for (int o = 16; o; o >>= 1) {
        lmin = fminf(lmin, __shfl_xor_sync(0xFFFFFFFFu, lmin, o));
        lmax = fmaxf(lmax, __shfl_xor_sync(0xFFFFFFFFu, lmax, o));
    }
    __shared__ float smin[8], smax[8];
    int warp = threadIdx.x >> 5, lane = threadIdx.x & 31;
    if (lane == 0) { smin[warp] = lmin; smax[warp] = lmax; }
    __syncthreads();
    if (threadIdx.x == 0) {
        for (int w = 1; w < 8; w++) {
            lmin = fminf(lmin, smin[w]);
            lmax = fmaxf(lmax, smax[w]);
        }
        if (sel == 0) {
            atomicMin(&g_xmin_u, fenc(lmin));
            atomicMax(&g_xmax_u, fenc(lmax));
        } else {
            atomicMin(&g_wmin_u, fenc(lmin));
            atomicMax(&g_wmax_u, fenc(lmax));
        }
    }
}

// quantize one value exactly like the reference:
//   clip((t - zero)/scale - 4, -4, 3).astype(int32)  [trunc toward zero]
__device__ __forceinline__ int quant1(float t, float zero, float scale) {
    float v = __fdiv_rn(t - zero, scale) - 4.0f;   // IEEE div even w/ fast-math
    v = fminf(fmaxf(v, -4.0f), 3.0f);
    return (int)v;                                  // trunc toward zero
}

__device__ __forceinline__ unsigned packq2(float a, float b, float zero, float scale) {
    __nv_bfloat162 h = __floats2bfloat162_rn((float)quant1(a, zero, scale),
                                             (float)quant1(b, zero, scale));
    return *reinterpret_cast<unsigned*>(&h);
}

// ---------------------------------------------------------------------------
// Quantize x -> g_xq (bf16 integers)
// ---------------------------------------------------------------------------
__global__ void quantx_kernel(const float4* __restrict__ x) {
    float zero = fdec(g_xmin_u);
    float scale = (fdec(g_xmax_u) - zero) * 0.125f;
    uint2* dst = reinterpret_cast<uint2*>(g_xq);
    const int n4 = (MDIM * KDIM) / 4;
    for (int i = blockIdx.x * blockDim.x + threadIdx.x; i < n4;
         i += gridDim.x * blockDim.x) {
        float4 v = x[i];
        uint2 u;
        u.x = packq2(v.x, v.y, zero, scale);
        u.y = packq2(v.z, v.w, zero, scale);
        dst[i] = u;
    }
}

// ---------------------------------------------------------------------------
// Quantize w row -> g_wq, fused fp32 row sum -> g_wsum. One block per row.
// ---------------------------------------------------------------------------
__global__ void quantw_kernel(const float* __restrict__ w) {
    int row = blockIdx.x;
    int tid = threadIdx.x;
    float zero = fdec(g_wmin_u);
    float scale = (fdec(g_wmax_u) - zero) * 0.125f;
    const float4* src = reinterpret_cast<const float4*>(w + (size_t)row * KDIM);
    uint2* dst = reinterpret_cast<uint2*>(g_wq + (size_t)row * KDIM);
    float sum = 0.0f;
    for (int i = tid; i < KDIM / 4; i += 256) {
        float4 v = src[i];
        sum += (v.x + v.y) + (v.z + v.w);
        uint2 u;
        u.x = packq2(v.x, v.y, zero, scale);
        u.y = packq2(v.z, v.w, zero, scale);
        dst[i] = u;
    }
#pragma unroll
    for (int o = 16; o; o >>= 1) sum += __shfl_xor_sync(0xFFFFFFFFu, sum, o);
    __shared__ float ssum[8];
    int warp = tid >> 5, lane = tid & 31;
    if (lane == 0) ssum[warp] = sum;
    __syncthreads();
    if (tid == 0) {
        float t = ssum[0];
        for (int wq = 1; wq < 8; wq++) t += ssum[wq];
        g_wsum[row] = t;
    }
}

// ---------------------------------------------------------------------------
// GEMM: C = Xq (MxK) * Wq^T (NxK row-major) with dequant epilogue.
// 128x128 block tile, BK=32, 8 warps (2x4), warp tile 64x32,
// cp.async double-buffered smem, ldmatrix + mma.sync.m16n8k16 bf16/f32.
// ---------------------------------------------------------------------------
__device__ __forceinline__ void cp_async16(uint32_t dst, const void* src) {
    asm volatile("cp.async.cg.shared.global [%0], [%1], 16;\n" :: "r"(dst), "l"(src));
}
__device__ __forceinline__ void cp_commit() {
    asm volatile("cp.async.commit_group;\n");
}
__device__ __forceinline__ void cp_wait0() {
    asm volatile("cp.async.wait_group 0;\n");
}
__device__ __forceinline__ void ldm_x4(uint32_t addr, uint32_t& r0, uint32_t& r1,
                                       uint32_t& r2, uint32_t& r3) {
    asm volatile("ldmatrix.sync.aligned.m8n8.x4.shared.b16 {%0,%1,%2,%3}, [%4];"
                 : "=r"(r0), "=r"(r1), "=r"(r2), "=r"(r3) : "r"(addr));
}
__device__ __forceinline__ void mma16816(float* c, const uint32_t* a, const uint32_t* b) {
    asm volatile(
        "mma.sync.aligned.m16n8k16.row.col.f32.bf16.bf16.f32 "
        "{%0,%1,%2,%3}, {%4,%5,%6,%7}, {%8,%9}, {%0,%1,%2,%3};"
        : "+f"(c[0]), "+f"(c[1]), "+f"(c[2]), "+f"(c[3])
        : "r"(a[0]), "r"(a[1]), "r"(a[2]), "r"(a[3]), "r"(b[0]), "r"(b[1]));
}

__global__ __launch_bounds__(256) void gemm_kernel(const float* __restrict__ bias,
                                                   float* __restrict__ out) {
    __shared__ __nv_bfloat16 As[2][BM][LDS_A];
    __shared__ __nv_bfloat16 Bs[2][BN][LDS_A];

    const int tid = threadIdx.x;
    const int warp = tid >> 5, lane = tid & 31;
    const int wm = warp & 1;   // 0..1 -> m offset wm*64
    const int wn = warp >> 1;  // 0..3 -> n offset wn*32
    const int bm0 = blockIdx.y * BM;
    const int bn0 = blockIdx.x * BN;

    const uint32_t sA = (uint32_t)__cvta_generic_to_shared(&As[0][0][0]);
    const uint32_t sB = (uint32_t)__cvta_generic_to_shared(&Bs[0][0][0]);
    const uint32_t BUFB = BM * LDS_A * 2;  // bytes per buffer (A and B identical)

    float acc[4][4][4];
#pragma unroll
    for (int mi = 0; mi < 4; mi++)
#pragma unroll
        for (int nf = 0; nf < 4; nf++)
#pragma unroll
            for (int e = 0; e < 4; e++) acc[mi][nf][e] = 0.0f;

    auto load_tiles = [&](int buf, int k0) {
#pragma unroll
        for (int it = 0; it < 2; it++) {
            int c = tid + it * 256;        // 0..511
            int row = c >> 2;              // 0..127
            int col = (c & 3) << 3;        // 0,8,16,24 (bf16 elems; 16B chunk)
            const __nv_bfloat16* srcA = g_xq + (size_t)(bm0 + row) * KDIM + k0 + col;
            cp_async16(sA + (uint32_t)buf * BUFB + (uint32_t)(row * LDS_A + col) * 2, srcA);
            const __nv_bfloat16* srcB = g_wq + (size_t)(bn0 + row) * KDIM + k0 + col;
            cp_async16(sB + (uint32_t)buf * BUFB + (uint32_t)(row * LDS_A + col) * 2, srcB);
        }
    };

    auto compute = [&](int buf) {
#pragma unroll
        for (int ks = 0; ks < 2; ks++) {
            const int ko = ks * 16;
            uint32_t a[4][4];
#pragma unroll
            for (int mi = 0; mi < 4; mi++) {
                int m = wm * 64 + mi * 16 + (lane & 15);
                int col = ko + ((lane >> 4) << 3);
                uint32_t addr = sA + (uint32_t)buf * BUFB + (uint32_t)(m * LDS_A + col) * 2;
                ldm_x4(addr, a[mi][0], a[mi][1], a[mi][2], a[mi][3]);
            }
            uint32_t b[4][2];
#pragma unroll
            for (int half = 0; half < 2; half++) {
                int n = wn * 32 + half * 16 + ((lane >> 4) & 1) * 8 + (lane & 7);
                int col = ko + ((lane >> 3) & 1) * 8;
                uint32_t addr = sB + (uint32_t)buf * BUFB + (uint32_t)(n * LDS_A + col) * 2;
                uint32_t r0, r1, r2, r3;
                ldm_x4(addr, r0, r1, r2, r3);
                b[half * 2][0] = r0;     b[half * 2][1] = r1;
                b[half * 2 + 1][0] = r2; b[half * 2 + 1][1] = r3;
            }
#pragma unroll
            for (int mi = 0; mi < 4; mi++)
#pragma unroll
                for (int nf = 0; nf < 4; nf++)
                    mma16816(acc[mi][nf], a[mi], b[nf]);
        }
    };

    const int KT = KDIM / BK;  // 128
    load_tiles(0, 0);
    cp_commit();
    cp_wait0();
    __syncthreads();
    for (int kt = 0; kt < KT; kt++) {
        int cur = kt & 1;
        if (kt + 1 < KT) {
            load_tiles(cur ^ 1, (kt + 1) * BK);
            cp_commit();
        }
        compute(cur);
        if (kt + 1 < KT) cp_wait0();
        __syncthreads();
    }

    // ---- dequant epilogue ----
    const float zx = fdec(g_xmin_u);
    const float sa = (fdec(g_xmax_u) - zx) * 0.125f;
    const float zw = fdec(g_wmin_u);
    const float sw = (fdec(g_wmax_u) - zw) * 0.125f;
    const float s = sa * sw;
    const float coef = zx + 4.0f * sa;
    const int gid = lane >> 2, tig = lane & 3;

#pragma unroll
    for (int mi = 0; mi < 4; mi++) {
        int r0 = bm0 + wm * 64 + mi * 16 + gid;
        float ws0 = coef * g_wsum[r0];
        float ws1 = coef * g_wsum[r0 + 8];
#pragma unroll
        for (int nf = 0; nf < 4; nf++) {
            int c0 = bn0 + wn * 32 + nf * 8 + tig * 2;
            float b0 = bias[c0], b1 = bias[c0 + 1];
            out[(size_t)r0 * NDIM + c0]           = (acc[mi][nf][0] + b0) * s + ws0;
            out[(size_t)r0 * NDIM + c0 + 1]       = (acc[mi][nf][1] + b1) * s + ws0;
            out[(size_t)(r0 + 8) * NDIM + c0]     = (acc[mi][nf][2] + b0) * s + ws1;
            out[(size_t)(r0 + 8) * NDIM + c0 + 1] = (acc[mi][nf][3] + b1) * s + ws1;
        }
    }
}

// ---------------------------------------------------------------------------
extern "C" void kernel_launch(void* const* d_in, const int* in_sizes, int n_in,
                              void* d_out, int out_size) {
    const float* x    = (const float*)d_in[0];   // [4096, 4096]
    const float* w    = (const float*)d_in[1];   // [4096, 4096]
    const float* bias = (const float*)d_in[2];   // [4096]
    float* out = (float*)d_out;                  // [4096, 4096]
    (void)in_sizes; (void)n_in; (void)out_size;

    init_kernel<<<1, 1>>>();
    const int n4 = (MDIM * KDIM) / 4;
    minmax_kernel<<<1024, 256>>>((const float4*)x, n4, 0);
    minmax_kernel<<<1024, 256>>>((const float4*)w, n4, 1);
    quantx_kernel<<<8192, 256>>>((const float4*)x);
    quantw_kernel<<<NDIM, 256>>>(w);
    dim3 grid(NDIM / BN, MDIM / BM);
    gemm_kernel<<<grid, 256>>>(bias, out);
}